// round 8
// baseline (speedup 1.0000x reference)
#include <cuda_runtime.h>
#include <cuda_bf16.h>
#include <cuda_fp8.h>
#include <stdint.h>

#define ATOMS   4096
#define DMODEL  16384
#define BATCH   32
#define ITERS   10
#define TEMP    0.001f

#define KCHUNKS 8
#define KCHUNK  (DMODEL / KCHUNKS)   // 2048
#define ATILE   64
#define NTILES  (ATOMS / ATILE)      // 64
#define KB      128                  // fp8 k elems per stage
#define NSTAGE  3
#define NSTEPS  (KCHUNK / KB)        // 16
#define MAXC    64
#define WINDOW  0.40f                // 6.2 sigma of fp8 score noise

#define DSCALE  8192.0f
#define RSCALE  32.0f
#define INV_S   (1.0f / (DSCALE * RSCALE))

#define SROW    (KB + 16)            // 144

#define NRES (BATCH * DMODEL)        // 524288

// ---------------- persistent scratch --------------------------------------
__device__ uint8_t g_dict_f8[(size_t)ATOMS * DMODEL];              // 64 MB (L2-resident)
__device__ float   g_resid[(size_t)BATCH * DMODEL];                // 2 MB
__device__ uint8_t g_resid_f8[(size_t)BATCH * DMODEL];             // 0.5 MB
__device__ float   g_part[(size_t)KCHUNKS * BATCH * ATOMS];        // 4 MB
__device__ int     g_cand[BATCH * MAXC];
__device__ float   g_ex[BATCH * MAXC];
__device__ int     g_n[BATCH];
__device__ float   g_lpart[512];

// ---------------- PTX helpers ----------------------------------------------
__device__ __forceinline__ uint32_t smem_u32(const void* p) {
    return (uint32_t)__cvta_generic_to_shared(p);
}
__device__ __forceinline__ void cpa16(uint32_t s, const void* g) {
    asm volatile("cp.async.cg.shared.global [%0], [%1], 16;\n" :: "r"(s), "l"(g));
}
__device__ __forceinline__ void cpa_commit() {
    asm volatile("cp.async.commit_group;\n");
}
__device__ __forceinline__ void cpa_wait2() {
    asm volatile("cp.async.wait_group 2;\n");
}
__device__ __forceinline__ void ldsm_x4(uint32_t* r, uint32_t addr) {
    asm volatile("ldmatrix.sync.aligned.m8n8.x4.shared.b16 {%0,%1,%2,%3}, [%4];\n"
        : "=r"(r[0]), "=r"(r[1]), "=r"(r[2]), "=r"(r[3]) : "r"(addr));
}
__device__ __forceinline__ void ldsm_x2(uint32_t* r, uint32_t addr) {
    asm volatile("ldmatrix.sync.aligned.m8n8.x2.shared.b16 {%0,%1}, [%2];\n"
        : "=r"(r[0]), "=r"(r[1]) : "r"(addr));
}
__device__ __forceinline__ void mma16832(float* c, const uint32_t* a, const uint32_t* b) {
    asm volatile(
        "mma.sync.aligned.m16n8k32.row.col.f32.e4m3.e4m3.f32 "
        "{%0,%1,%2,%3}, {%4,%5,%6,%7}, {%8,%9}, {%0,%1,%2,%3};\n"
        : "+f"(c[0]), "+f"(c[1]), "+f"(c[2]), "+f"(c[3])
        : "r"(a[0]), "r"(a[1]), "r"(a[2]), "r"(a[3]), "r"(b[0]), "r"(b[1]));
}
__device__ __forceinline__ uint32_t f8x4(float x, float y, float z, float w) {
    __nv_fp8x4_e4m3 p(make_float4(x, y, z, w));
    return *(uint32_t*)&p;
}

// ---------------- kernels ---------------------------------------------------

__global__ void k_convert_dict(const float* __restrict__ dict) {
    size_t i = ((size_t)blockIdx.x * blockDim.x + threadIdx.x) * 4;
    float4 v = *(const float4*)(dict + i);
    *(uint32_t*)(g_dict_f8 + i) =
        f8x4(v.x * DSCALE, v.y * DSCALE, v.z * DSCALE, v.w * DSCALE);
}

__global__ void k_init(const float* __restrict__ x) {
    size_t i = ((size_t)blockIdx.x * blockDim.x + threadIdx.x) * 4;
    float4 v = *(const float4*)(x + i);
    *(float4*)(g_resid + i) = v;
    *(uint32_t*)(g_resid_f8 + i) =
        f8x4(v.x * RSCALE, v.y * RSCALE, v.z * RSCALE, v.w * RSCALE);
}

// Approx scores (fp8 tensor cores), 3-stage cp.async pipeline (R4-proven).
// grid (NTILES=64, KCHUNKS=8) = 512 CTAs, 256 threads (8 warps x 8 atoms).
__global__ void __launch_bounds__(256) k_scores() {
    __shared__ uint8_t sD[NSTAGE][ATILE][SROW];
    __shared__ uint8_t sR[NSTAGE][BATCH][SROW];

    const int t = threadIdx.x;
    const int lane = t & 31, warp = t >> 5;
    const int atomBase = blockIdx.x * ATILE;
    const int kBase = blockIdx.y * KCHUNK;

    float c0[4] = {0.f, 0.f, 0.f, 0.f};
    float c1[4] = {0.f, 0.f, 0.f, 0.f};

    const int arow = lane & 15;
    const int acolsel = (lane & 16) ? 16 : 0;
    const int brow = warp * 8 + (lane & 7);
    const int bcolsel = (lane & 8) ? 16 : 0;

    const int dr0 = t >> 3, ds = t & 7;
    const int dr1 = dr0 + 32;
    const int rr = t >> 3, rs = t & 7;

    auto load_stage = [&](int buf, int kb) {
        const size_t gk = (size_t)(kBase + kb);
        cpa16(smem_u32(&sD[buf][dr0][ds * 16]),
              &g_dict_f8[(size_t)(atomBase + dr0) * DMODEL + gk + ds * 16]);
        cpa16(smem_u32(&sD[buf][dr1][ds * 16]),
              &g_dict_f8[(size_t)(atomBase + dr1) * DMODEL + gk + ds * 16]);
        cpa16(smem_u32(&sR[buf][rr][rs * 16]),
              &g_resid_f8[(size_t)rr * DMODEL + gk + rs * 16]);
        cpa_commit();
    };

    load_stage(0, 0);
    load_stage(1, KB);

    for (int s = 0; s < NSTEPS; s++) {
        if (s + NSTAGE - 1 < NSTEPS) load_stage((s + NSTAGE - 1) % NSTAGE, (s + NSTAGE - 1) * KB);
        else cpa_commit();
        cpa_wait2();
        __syncthreads();

        const int b = s % NSTAGE;
        #pragma unroll
        for (int ks = 0; ks < KB / 32; ks++) {
            uint32_t a0[4], a1[4], bb[2];
            const int col = ks * 32;
            ldsm_x4(a0, smem_u32(&sR[b][arow][col + acolsel]));
            ldsm_x4(a1, smem_u32(&sR[b][16 + arow][col + acolsel]));
            ldsm_x2(bb, smem_u32(&sD[b][brow][col + bcolsel]));
            mma16832(c0, a0, bb);
            mma16832(c1, a1, bb);
        }
        __syncthreads();
    }

    const int gr = lane >> 2;
    const int acol = atomBase + warp * 8 + (lane & 3) * 2;
    float* P = g_part + (size_t)blockIdx.y * BATCH * ATOMS;
    P[(size_t)(gr + 0)  * ATOMS + acol]     = c0[0];
    P[(size_t)(gr + 0)  * ATOMS + acol + 1] = c0[1];
    P[(size_t)(gr + 8)  * ATOMS + acol]     = c0[2];
    P[(size_t)(gr + 8)  * ATOMS + acol + 1] = c0[3];
    P[(size_t)(gr + 16) * ATOMS + acol]     = c1[0];
    P[(size_t)(gr + 16) * ATOMS + acol + 1] = c1[1];
    P[(size_t)(gr + 24) * ATOMS + acol]     = c1[2];
    P[(size_t)(gr + 24) * ATOMS + acol + 1] = c1[3];
}

// Fused reduce + select + exact fp32 rescore. grid (8, 32) x 256.
// Each of the 8 CTAs per row redundantly reduces that row's partials
// (L2-hot; deterministic) and computes the identical candidate list,
// then CTA cslot rescores candidates j = cslot, cslot+8, ...
__global__ void __launch_bounds__(256) k_rescore(const float* __restrict__ dict) {
    __shared__ float s_scores[ATOMS];   // 16 KB
    __shared__ float sred[8];
    __shared__ int   s_cnt, s_n;
    __shared__ int   s_idx[MAXC];

    const int cslot = blockIdx.x, r = blockIdx.y, t = threadIdx.x;
    const int lane = t & 31, w = t >> 5;

    if (t == 0) s_cnt = 0;

    // reduce 8 K-chunk partials into true-unit scores (smem), track max
    float lmax = -1e30f;
    #pragma unroll
    for (int i = 0; i < 4; i++) {
        const int a4 = (i * 256 + t) * 4;
        float4 s = make_float4(0.f, 0.f, 0.f, 0.f);
        #pragma unroll
        for (int c = 0; c < KCHUNKS; c++) {
            const float4 p = *(const float4*)&g_part[((size_t)c * BATCH + r) * ATOMS + a4];
            s.x += p.x; s.y += p.y; s.z += p.z; s.w += p.w;
        }
        s.x *= INV_S; s.y *= INV_S; s.z *= INV_S; s.w *= INV_S;
        *(float4*)&s_scores[a4] = s;
        lmax = fmaxf(lmax, fmaxf(fmaxf(s.x, s.y), fmaxf(s.z, s.w)));
    }
    #pragma unroll
    for (int o = 16; o > 0; o >>= 1) lmax = fmaxf(lmax, __shfl_xor_sync(0xffffffffu, lmax, o));
    if (lane == 0) sred[w] = lmax;
    __syncthreads();
    float thr;
    {
        float mm = sred[0];
        #pragma unroll
        for (int i = 1; i < 8; i++) mm = fmaxf(mm, sred[i]);
        thr = mm - WINDOW;
    }

    // candidate selection (identical across the 8 CTAs after sort)
    #pragma unroll
    for (int i = 0; i < 16; i++) {
        const int a = i * 256 + t;
        if (s_scores[a] > thr) {
            int p = atomicAdd(&s_cnt, 1);
            if (p < MAXC) s_idx[p] = a;
        }
    }
    __syncthreads();
    if (t == 0) {
        int n = min(s_cnt, MAXC);
        for (int i = 1; i < n; i++) {
            int v = s_idx[i], j = i - 1;
            while (j >= 0 && s_idx[j] > v) { s_idx[j + 1] = s_idx[j]; j--; }
            s_idx[j + 1] = v;
        }
        s_n = n;
        if (cslot == 0) {
            g_n[r] = n;
            for (int i = 0; i < n; i++) g_cand[r * MAXC + i] = s_idx[i];
        }
    }
    __syncthreads();
    const int n = s_n;

    // exact fp32 rescore of this CTA's candidate slice
    const float* R = g_resid + (size_t)r * DMODEL;
    for (int j = cslot; j < n; j += 8) {
        const float* D = dict + (size_t)s_idx[j] * DMODEL;
        float acc = 0.f;
        #pragma unroll 4
        for (int d = t * 4; d < DMODEL; d += 1024) {
            const float4 rv = *(const float4*)(R + d);
            const float4 dv = *(const float4*)(D + d);
            acc += rv.x * dv.x + rv.y * dv.y + rv.z * dv.z + rv.w * dv.w;
        }
        #pragma unroll
        for (int o = 16; o > 0; o >>= 1) acc += __shfl_xor_sync(0xffffffffu, acc, o);
        if (lane == 0) sred[w] = acc;
        __syncthreads();
        if (t == 0) {
            float s = 0.f;
            #pragma unroll
            for (int i = 0; i < 8; i++) s += sred[i];
            g_ex[r * MAXC + j] = s;
        }
        __syncthreads();
    }
}

// Sparse residual update + fp8 mirror; per-CTA softmax (n small, deterministic).
// grid (16, 32) x 256.
__global__ void __launch_bounds__(256) k_apply(const float* __restrict__ dict) {
    __shared__ float s_w[MAXC];
    __shared__ int   s_c[MAXC];
    const int cb = blockIdx.x, r = blockIdx.y, t = threadIdx.x;
    const int n = g_n[r];

    if (t == 0) {
        float em = -1e30f;
        for (int j = 0; j < n; j++) em = fmaxf(em, g_ex[r * MAXC + j]);
        float den = 0.f;
        for (int j = 0; j < n; j++) {
            const float wv = expf((g_ex[r * MAXC + j] - em) / TEMP);
            s_w[j] = wv; den += wv;
        }
        const float inv = 1.f / den;
        for (int j = 0; j < n; j++) s_w[j] *= inv;
    }
    if (t < MAXC) s_c[t] = g_cand[r * MAXC + t];
    __syncthreads();

    const int col = cb * 1024 + t * 4;
    const size_t base = (size_t)r * DMODEL + col;

    float4 v = *(const float4*)(g_resid + base);
    for (int j = 0; j < n; j++) {
        const float wj = s_w[j];
        const float4 dv = *(const float4*)(dict + (size_t)s_c[j] * DMODEL + col);
        v.x -= wj * dv.x; v.y -= wj * dv.y; v.z -= wj * dv.z; v.w -= wj * dv.w;
    }
    *(float4*)(g_resid + base) = v;
    *(uint32_t*)(g_resid_f8 + base) =
        f8x4(v.x * RSCALE, v.y * RSCALE, v.z * RSCALE, v.w * RSCALE);
}

// Fused epilogue: copy residual to out AND per-block square-sums.
__global__ void k_epilogue(float* out, int out_size) {
    __shared__ float s[256];
    const int b = blockIdx.x, t = threadIdx.x;
    const int off = (out_size > NRES) ? 1 : 0;
    const size_t base = (size_t)b * 1024;
    float acc = 0.f;
    #pragma unroll
    for (int i = 0; i < 4; i++) {
        const size_t idx = base + t + i * 256;
        const float v = g_resid[idx];
        out[off + idx] = v;
        acc += v * v;
    }
    s[t] = acc; __syncthreads();
    for (int o = 128; o > 0; o >>= 1) { if (t < o) s[t] += s[t + o]; __syncthreads(); }
    if (t == 0) g_lpart[b] = s[0];
}

__global__ void k_finalize(float* out, int out_size) {
    __shared__ float s[512];
    const int t = threadIdx.x;
    s[t] = g_lpart[t]; __syncthreads();
    for (int o = 256; o > 0; o >>= 1) { if (t < o) s[t] += s[t + o]; __syncthreads(); }
    if (t == 0 && out_size > NRES) out[0] = s[0] / (float)NRES;
}

// ---------------- launch ----------------------------------------------------
extern "C" void kernel_launch(void* const* d_in, const int* in_sizes, int n_in,
                              void* d_out, int out_size) {
    const float* x = nullptr;
    const float* dict = nullptr;
    for (int i = 0; i < n_in; i++) {
        if (in_sizes[i] == NRES) x = (const float*)d_in[i];
        else if (in_sizes[i] == ATOMS * DMODEL) dict = (const float*)d_in[i];
    }
    float* out = (float*)d_out;

    k_convert_dict<<<65536, 256>>>(dict);
    k_init<<<512, 256>>>(x);

    for (int it = 0; it < ITERS; it++) {
        k_scores<<<dim3(NTILES, KCHUNKS), 256>>>();
        k_rescore<<<dim3(8, BATCH), 256>>>(dict);
        k_apply<<<dim3(16, BATCH), 256>>>(dict);
    }

    k_epilogue<<<512, 256>>>(out, out_size);
    k_finalize<<<1, 512>>>(out, out_size);
}

// round 9
// speedup vs baseline: 1.1126x; 1.1126x over previous
#include <cuda_runtime.h>
#include <cuda_bf16.h>
#include <cuda_fp8.h>
#include <stdint.h>

#define ATOMS   4096
#define DMODEL  16384
#define BATCH   32
#define ITERS   10
#define TEMP    0.001f

#define KCHUNKS 8
#define KCHUNK  (DMODEL / KCHUNKS)   // 2048
#define ATILE   64
#define NTILES  (ATOMS / ATILE)      // 64
#define KB      128                  // fp8 k elems per stage
#define NSTAGE  3
#define NSTEPS  (KCHUNK / KB)        // 16
#define MAXC    64
#define WINDOW  0.40f                // 6.2 sigma of fp8 score noise

#define DSCALE  8192.0f
#define RSCALE  32.0f
#define INV_S   (1.0f / (DSCALE * RSCALE))

#define SROW    (KB + 16)            // 144
#define NRES    (BATCH * DMODEL)     // 524288

#define GRID_U  256                  // k_update grid (8 x 32)

// ---------------- persistent scratch --------------------------------------
__device__ uint8_t  g_dict_f8[(size_t)ATOMS * DMODEL];              // 64 MB
__device__ float    g_resid[(size_t)BATCH * DMODEL];                // 2 MB
__device__ uint8_t  g_resid_f8[(size_t)BATCH * DMODEL];             // 0.5 MB
__device__ float    g_part[(size_t)KCHUNKS * BATCH * ATOMS];        // 4 MB
__device__ float    g_scores[(size_t)BATCH * ATOMS];                // 512 KB
__device__ unsigned g_rowmax[BATCH];
__device__ float    g_ex[BATCH * MAXC];
__device__ float    g_lpart[512];
__device__ unsigned g_bcnt[2];
__device__ unsigned g_bgen[2];

// ---------------- PTX helpers ----------------------------------------------
__device__ __forceinline__ uint32_t smem_u32(const void* p) {
    return (uint32_t)__cvta_generic_to_shared(p);
}
__device__ __forceinline__ void cpa16(uint32_t s, const void* g) {
    asm volatile("cp.async.cg.shared.global [%0], [%1], 16;\n" :: "r"(s), "l"(g));
}
__device__ __forceinline__ void cpa_commit() {
    asm volatile("cp.async.commit_group;\n");
}
__device__ __forceinline__ void cpa_wait2() {
    asm volatile("cp.async.wait_group 2;\n");
}
__device__ __forceinline__ void ldsm_x4(uint32_t* r, uint32_t addr) {
    asm volatile("ldmatrix.sync.aligned.m8n8.x4.shared.b16 {%0,%1,%2,%3}, [%4];\n"
        : "=r"(r[0]), "=r"(r[1]), "=r"(r[2]), "=r"(r[3]) : "r"(addr));
}
__device__ __forceinline__ void ldsm_x2(uint32_t* r, uint32_t addr) {
    asm volatile("ldmatrix.sync.aligned.m8n8.x2.shared.b16 {%0,%1}, [%2];\n"
        : "=r"(r[0]), "=r"(r[1]) : "r"(addr));
}
__device__ __forceinline__ void mma16832(float* c, const uint32_t* a, const uint32_t* b) {
    asm volatile(
        "mma.sync.aligned.m16n8k32.row.col.f32.e4m3.e4m3.f32 "
        "{%0,%1,%2,%3}, {%4,%5,%6,%7}, {%8,%9}, {%0,%1,%2,%3};\n"
        : "+f"(c[0]), "+f"(c[1]), "+f"(c[2]), "+f"(c[3])
        : "r"(a[0]), "r"(a[1]), "r"(a[2]), "r"(a[3]), "r"(b[0]), "r"(b[1]));
}
__device__ __forceinline__ uint32_t f8x4(float x, float y, float z, float w) {
    __nv_fp8x4_e4m3 p(make_float4(x, y, z, w));
    return *(uint32_t*)&p;
}
__device__ __forceinline__ unsigned fenc(float v) {
    int b = __float_as_int(v);
    return (b >= 0) ? ((unsigned)b | 0x80000000u) : ~(unsigned)b;
}
__device__ __forceinline__ float fdec(unsigned k) {
    int b = (k & 0x80000000u) ? (int)(k & 0x7fffffffu) : ~(int)k;
    return __int_as_float(b);
}

// Generation-counter grid barrier: safe across launches/replays (no reset).
__device__ __forceinline__ void gbar(int b) {
    __syncthreads();
    if (threadIdx.x == 0) {
        volatile unsigned* gen = &g_bgen[b];
        const unsigned g = *gen;
        __threadfence();
        const unsigned o = atomicAdd(&g_bcnt[b], 1u);
        if (o == GRID_U - 1) {
            g_bcnt[b] = 0;
            __threadfence();
            atomicAdd(&g_bgen[b], 1u);
        } else {
            while (*gen == g) __nanosleep(64);
        }
        __threadfence();
    }
    __syncthreads();
}

// ---------------- kernels ---------------------------------------------------

__global__ void k_convert_dict(const float* __restrict__ dict) {
    size_t i = ((size_t)blockIdx.x * blockDim.x + threadIdx.x) * 4;
    float4 v = *(const float4*)(dict + i);
    *(uint32_t*)(g_dict_f8 + i) =
        f8x4(v.x * DSCALE, v.y * DSCALE, v.z * DSCALE, v.w * DSCALE);
}

__global__ void k_init(const float* __restrict__ x) {
    size_t i = ((size_t)blockIdx.x * blockDim.x + threadIdx.x) * 4;
    float4 v = *(const float4*)(x + i);
    *(float4*)(g_resid + i) = v;
    *(uint32_t*)(g_resid_f8 + i) =
        f8x4(v.x * RSCALE, v.y * RSCALE, v.z * RSCALE, v.w * RSCALE);
    if (blockIdx.x == 0 && threadIdx.x < BATCH) g_rowmax[threadIdx.x] = 0u;
}

// Approx scores (fp8 tensor cores), 3-stage cp.async pipeline (R4-proven).
// grid (64, 8) = 512 CTAs, 256 threads (8 warps x 8 atoms).
__global__ void __launch_bounds__(256) k_scores() {
    __shared__ uint8_t sD[NSTAGE][ATILE][SROW];
    __shared__ uint8_t sR[NSTAGE][BATCH][SROW];

    const int t = threadIdx.x;
    const int lane = t & 31, warp = t >> 5;
    const int atomBase = blockIdx.x * ATILE;
    const int kBase = blockIdx.y * KCHUNK;

    float c0[4] = {0.f, 0.f, 0.f, 0.f};
    float c1[4] = {0.f, 0.f, 0.f, 0.f};

    const int arow = lane & 15;
    const int acolsel = (lane & 16) ? 16 : 0;
    const int brow = warp * 8 + (lane & 7);
    const int bcolsel = (lane & 8) ? 16 : 0;

    const int dr0 = t >> 3, ds = t & 7;
    const int dr1 = dr0 + 32;
    const int rr = t >> 3, rs = t & 7;

    auto load_stage = [&](int buf, int kb) {
        const size_t gk = (size_t)(kBase + kb);
        cpa16(smem_u32(&sD[buf][dr0][ds * 16]),
              &g_dict_f8[(size_t)(atomBase + dr0) * DMODEL + gk + ds * 16]);
        cpa16(smem_u32(&sD[buf][dr1][ds * 16]),
              &g_dict_f8[(size_t)(atomBase + dr1) * DMODEL + gk + ds * 16]);
        cpa16(smem_u32(&sR[buf][rr][rs * 16]),
              &g_resid_f8[(size_t)rr * DMODEL + gk + rs * 16]);
        cpa_commit();
    };

    load_stage(0, 0);
    load_stage(1, KB);

    for (int s = 0; s < NSTEPS; s++) {
        if (s + NSTAGE - 1 < NSTEPS) load_stage((s + NSTAGE - 1) % NSTAGE, (s + NSTAGE - 1) * KB);
        else cpa_commit();
        cpa_wait2();
        __syncthreads();

        const int b = s % NSTAGE;
        #pragma unroll
        for (int ks = 0; ks < KB / 32; ks++) {
            uint32_t a0[4], a1[4], bb[2];
            const int col = ks * 32;
            ldsm_x4(a0, smem_u32(&sR[b][arow][col + acolsel]));
            ldsm_x4(a1, smem_u32(&sR[b][16 + arow][col + acolsel]));
            ldsm_x2(bb, smem_u32(&sD[b][brow][col + bcolsel]));
            mma16832(c0, a0, bb);
            mma16832(c1, a1, bb);
        }
        __syncthreads();
    }

    const int gr = lane >> 2;
    const int acol = atomBase + warp * 8 + (lane & 3) * 2;
    float* P = g_part + (size_t)blockIdx.y * BATCH * ATOMS;
    P[(size_t)(gr + 0)  * ATOMS + acol]     = c0[0];
    P[(size_t)(gr + 0)  * ATOMS + acol + 1] = c0[1];
    P[(size_t)(gr + 8)  * ATOMS + acol]     = c0[2];
    P[(size_t)(gr + 8)  * ATOMS + acol + 1] = c0[3];
    P[(size_t)(gr + 16) * ATOMS + acol]     = c1[0];
    P[(size_t)(gr + 16) * ATOMS + acol + 1] = c1[1];
    P[(size_t)(gr + 24) * ATOMS + acol]     = c1[2];
    P[(size_t)(gr + 24) * ATOMS + acol + 1] = c1[3];
}

// Fused update: reduce -> gbar -> select+rescore -> gbar -> softmax+apply.
// grid (8, 32) x 256. All 256 CTAs co-resident (smem ~1KB, regs ~40).
__global__ void __launch_bounds__(256) k_update(const float* __restrict__ dict) {
    __shared__ float sred[8];
    __shared__ int   s_cnt, s_n;
    __shared__ int   s_idx[MAXC];
    __shared__ float s_w[MAXC];

    const int cslot = blockIdx.x, r = blockIdx.y, t = threadIdx.x;
    const int lane = t & 31, w = t >> 5;

    if (t == 0) s_cnt = 0;

    // ---- P1: reduce this CTA's 512-atom slice over 8 K-chunk partials ----
    float lmax = -1e30f;
    #pragma unroll
    for (int i = 0; i < 2; i++) {
        const int a = cslot * 512 + i * 256 + t;
        float s = 0.f;
        #pragma unroll
        for (int c = 0; c < KCHUNKS; c++)
            s += g_part[((size_t)c * BATCH + r) * ATOMS + a];
        s *= INV_S;
        g_scores[(size_t)r * ATOMS + a] = s;
        lmax = fmaxf(lmax, s);
    }
    #pragma unroll
    for (int o = 16; o > 0; o >>= 1) lmax = fmaxf(lmax, __shfl_xor_sync(0xffffffffu, lmax, o));
    if (lane == 0) sred[w] = lmax;
    __syncthreads();
    if (t == 0) {
        float mm = sred[0];
        #pragma unroll
        for (int i = 1; i < 8; i++) mm = fmaxf(mm, sred[i]);
        atomicMax(&g_rowmax[r], fenc(mm));
    }

    gbar(0);   // all rows' scores + maxes final

    // ---- P2: select (identical per-row list) + rescore slice ----
    const float thr = fdec(g_rowmax[r]) - WINDOW;
    #pragma unroll
    for (int i = 0; i < 16; i++) {
        const int a = i * 256 + t;
        if (g_scores[(size_t)r * ATOMS + a] > thr) {
            int p = atomicAdd(&s_cnt, 1);
            if (p < MAXC) s_idx[p] = a;
        }
    }
    __syncthreads();
    if (t == 0) {
        int n = min(s_cnt, MAXC);
        for (int i = 1; i < n; i++) {
            int v = s_idx[i], j = i - 1;
            while (j >= 0 && s_idx[j] > v) { s_idx[j + 1] = s_idx[j]; j--; }
            s_idx[j + 1] = v;
        }
        s_n = n;
    }
    __syncthreads();
    const int n = s_n;

    const float* R = g_resid + (size_t)r * DMODEL;
    for (int j = cslot; j < n; j += 8) {
        const float* D = dict + (size_t)s_idx[j] * DMODEL;
        float acc = 0.f;
        #pragma unroll 4
        for (int d = t * 4; d < DMODEL; d += 1024) {
            const float4 rv = *(const float4*)(R + d);
            const float4 dv = *(const float4*)(D + d);
            acc += rv.x * dv.x + rv.y * dv.y + rv.z * dv.z + rv.w * dv.w;
        }
        #pragma unroll
        for (int o = 16; o > 0; o >>= 1) acc += __shfl_xor_sync(0xffffffffu, acc, o);
        if (lane == 0) sred[w] = acc;
        __syncthreads();
        if (t == 0) {
            float s = 0.f;
            #pragma unroll
            for (int i = 0; i < 8; i++) s += sred[i];
            g_ex[r * MAXC + j] = s;
        }
        __syncthreads();
    }

    gbar(1);   // all exact scores final

    // ---- P3: softmax (deterministic, per CTA) + apply column slice ----
    if (t == 0) {
        float em = -1e30f;
        for (int j = 0; j < n; j++) em = fmaxf(em, g_ex[r * MAXC + j]);
        float den = 0.f;
        for (int j = 0; j < n; j++) {
            const float wv = expf((g_ex[r * MAXC + j] - em) / TEMP);
            s_w[j] = wv; den += wv;
        }
        const float inv = 1.f / den;
        for (int j = 0; j < n; j++) s_w[j] *= inv;
    }
    __syncthreads();

    #pragma unroll
    for (int i = 0; i < 2; i++) {
        const int col = cslot * 2048 + i * 1024 + t * 4;
        const size_t base = (size_t)r * DMODEL + col;
        float4 v = *(const float4*)(g_resid + base);
        for (int j = 0; j < n; j++) {
            const float wj = s_w[j];
            const float4 dv = *(const float4*)(dict + (size_t)s_idx[j] * DMODEL + col);
            v.x -= wj * dv.x; v.y -= wj * dv.y; v.z -= wj * dv.z; v.w -= wj * dv.w;
        }
        *(float4*)(g_resid + base) = v;
        *(uint32_t*)(g_resid_f8 + base) =
            f8x4(v.x * RSCALE, v.y * RSCALE, v.z * RSCALE, v.w * RSCALE);
    }

    if (cslot == 0 && t == 0) g_rowmax[r] = 0u;   // reset for next iteration
}

// Fused epilogue: copy residual to out AND per-block square-sums.
__global__ void k_epilogue(float* out, int out_size) {
    __shared__ float s[256];
    const int b = blockIdx.x, t = threadIdx.x;
    const int off = (out_size > NRES) ? 1 : 0;
    const size_t base = (size_t)b * 1024;
    float acc = 0.f;
    #pragma unroll
    for (int i = 0; i < 4; i++) {
        const size_t idx = base + t + i * 256;
        const float v = g_resid[idx];
        out[off + idx] = v;
        acc += v * v;
    }
    s[t] = acc; __syncthreads();
    for (int o = 128; o > 0; o >>= 1) { if (t < o) s[t] += s[t + o]; __syncthreads(); }
    if (t == 0) g_lpart[b] = s[0];
}

__global__ void k_finalize(float* out, int out_size) {
    __shared__ float s[512];
    const int t = threadIdx.x;
    s[t] = g_lpart[t]; __syncthreads();
    for (int o = 256; o > 0; o >>= 1) { if (t < o) s[t] += s[t + o]; __syncthreads(); }
    if (t == 0 && out_size > NRES) out[0] = s[0] / (float)NRES;
}

// ---------------- launch ----------------------------------------------------
extern "C" void kernel_launch(void* const* d_in, const int* in_sizes, int n_in,
                              void* d_out, int out_size) {
    const float* x = nullptr;
    const float* dict = nullptr;
    for (int i = 0; i < n_in; i++) {
        if (in_sizes[i] == NRES) x = (const float*)d_in[i];
        else if (in_sizes[i] == ATOMS * DMODEL) dict = (const float*)d_in[i];
    }
    float* out = (float*)d_out;

    k_convert_dict<<<65536, 256>>>(dict);
    k_init<<<512, 256>>>(x);

    for (int it = 0; it < ITERS; it++) {
        k_scores<<<dim3(NTILES, KCHUNKS), 256>>>();
        k_update<<<dim3(8, BATCH), 256>>>(dict);
    }

    k_epilogue<<<512, 256>>>(out, out_size);
    k_finalize<<<1, 512>>>(out, out_size);
}

// round 10
// speedup vs baseline: 1.1699x; 1.0516x over previous
#include <cuda_runtime.h>
#include <cuda_bf16.h>
#include <cuda_fp8.h>
#include <stdint.h>

#define ATOMS   4096
#define DMODEL  16384
#define BATCH   32
#define ITERS   10
#define TEMP    0.001f

#define KCHUNKS 8
#define KCHUNK  (DMODEL / KCHUNKS)   // 2048
#define ATILE   64
#define NTILES  (ATOMS / ATILE)      // 64
#define KB      128
#define NSTAGE  3
#define NSTEPS  (KCHUNK / KB)        // 16
#define MAXC    64
#define WINDOW  0.40f

#define DSCALE  8192.0f
#define RSCALE  32.0f
#define INV_S   (1.0f / (DSCALE * RSCALE))

#define SROW    (KB + 16)            // 144
#define NRES    (BATCH * DMODEL)     // 524288

#define GRID_I  512                  // k_iter grid (all co-resident: 4/SM x 148)
#define SLOTS   16                   // update slots per row

// ---------------- persistent scratch --------------------------------------
__device__ uint8_t  g_dict_f8[(size_t)ATOMS * DMODEL];              // 64 MB
__device__ float    g_resid[(size_t)BATCH * DMODEL];                // 2 MB
__device__ uint8_t  g_resid_f8[(size_t)BATCH * DMODEL];             // 0.5 MB
__device__ float    g_part[(size_t)KCHUNKS * BATCH * ATOMS];        // 4 MB
__device__ unsigned g_rowmax[BATCH];
__device__ int      g_cnt[BATCH];
__device__ int      g_cand[BATCH * MAXC];
__device__ float    g_ex[BATCH * MAXC];
__device__ float    g_lpart[512];
__device__ unsigned g_bcnt[2];
__device__ unsigned g_bgen[2];

// ---------------- PTX helpers ----------------------------------------------
__device__ __forceinline__ uint32_t smem_u32(const void* p) {
    return (uint32_t)__cvta_generic_to_shared(p);
}
__device__ __forceinline__ void cpa16(uint32_t s, const void* g) {
    asm volatile("cp.async.cg.shared.global [%0], [%1], 16;\n" :: "r"(s), "l"(g));
}
__device__ __forceinline__ void cpa_commit() {
    asm volatile("cp.async.commit_group;\n");
}
__device__ __forceinline__ void cpa_wait2() {
    asm volatile("cp.async.wait_group 2;\n");
}
__device__ __forceinline__ void cpa_wait0() {
    asm volatile("cp.async.wait_group 0;\n");
}
__device__ __forceinline__ void ldsm_x4(uint32_t* r, uint32_t addr) {
    asm volatile("ldmatrix.sync.aligned.m8n8.x4.shared.b16 {%0,%1,%2,%3}, [%4];\n"
        : "=r"(r[0]), "=r"(r[1]), "=r"(r[2]), "=r"(r[3]) : "r"(addr));
}
__device__ __forceinline__ void ldsm_x2(uint32_t* r, uint32_t addr) {
    asm volatile("ldmatrix.sync.aligned.m8n8.x2.shared.b16 {%0,%1}, [%2];\n"
        : "=r"(r[0]), "=r"(r[1]) : "r"(addr));
}
__device__ __forceinline__ void mma16832(float* c, const uint32_t* a, const uint32_t* b) {
    asm volatile(
        "mma.sync.aligned.m16n8k32.row.col.f32.e4m3.e4m3.f32 "
        "{%0,%1,%2,%3}, {%4,%5,%6,%7}, {%8,%9}, {%0,%1,%2,%3};\n"
        : "+f"(c[0]), "+f"(c[1]), "+f"(c[2]), "+f"(c[3])
        : "r"(a[0]), "r"(a[1]), "r"(a[2]), "r"(a[3]), "r"(b[0]), "r"(b[1]));
}
__device__ __forceinline__ uint32_t f8x4(float x, float y, float z, float w) {
    __nv_fp8x4_e4m3 p(make_float4(x, y, z, w));
    return *(uint32_t*)&p;
}
__device__ __forceinline__ unsigned fenc(float v) {
    int b = __float_as_int(v);
    return (b >= 0) ? ((unsigned)b | 0x80000000u) : ~(unsigned)b;
}
__device__ __forceinline__ float fdec(unsigned k) {
    int b = (k & 0x80000000u) ? (int)(k & 0x7fffffffu) : ~(int)k;
    return __int_as_float(b);
}

// Generation-counter grid barrier (no reset needed across launches/replays).
__device__ __forceinline__ void gbar(int b) {
    __syncthreads();
    if (threadIdx.x == 0) {
        volatile unsigned* gen = &g_bgen[b];
        const unsigned g = *gen;
        __threadfence();
        const unsigned o = atomicAdd(&g_bcnt[b], 1u);
        if (o == GRID_I - 1) {
            g_bcnt[b] = 0;
            __threadfence();
            atomicAdd(&g_bgen[b], 1u);
        } else {
            while (*gen == g) __nanosleep(64);
        }
        __threadfence();
    }
    __syncthreads();
}

// ---------------- kernels ---------------------------------------------------

__global__ void k_convert_dict(const float* __restrict__ dict) {
    size_t i = ((size_t)blockIdx.x * blockDim.x + threadIdx.x) * 4;
    float4 v = *(const float4*)(dict + i);
    *(uint32_t*)(g_dict_f8 + i) =
        f8x4(v.x * DSCALE, v.y * DSCALE, v.z * DSCALE, v.w * DSCALE);
}

__global__ void k_init(const float* __restrict__ x) {
    size_t i = ((size_t)blockIdx.x * blockDim.x + threadIdx.x) * 4;
    float4 v = *(const float4*)(x + i);
    *(float4*)(g_resid + i) = v;
    *(uint32_t*)(g_resid_f8 + i) =
        f8x4(v.x * RSCALE, v.y * RSCALE, v.z * RSCALE, v.w * RSCALE);
    if (blockIdx.x == 0 && threadIdx.x < BATCH) {
        g_rowmax[threadIdx.x] = 0u;
        g_cnt[threadIdx.x] = 0;
    }
}

// One full MP iteration: scores -> reduce/select -> rescore -> apply.
// grid 512 x 256, all CTAs co-resident (launch_bounds forces 4/SM).
__global__ void __launch_bounds__(256, 4) k_iter(const float* __restrict__ dict) {
    __shared__ uint8_t sD[NSTAGE][ATILE][SROW];   // 27.0 KB
    __shared__ uint8_t sR[NSTAGE][BATCH][SROW];   // 13.5 KB
    __shared__ float   sred[8];
    __shared__ int     s_n;
    __shared__ int     s_idx[MAXC];
    __shared__ float   s_w[MAXC];

    const int t = threadIdx.x;
    const int lane = t & 31, warp = t >> 5;
    const int bx = blockIdx.x;

    // ================= Phase A: fp8 tensor-core scores =================
    {
        const int atomBase = (bx & (NTILES - 1)) * ATILE;
        const int kBase = (bx >> 6) * KCHUNK;

        float c0[4] = {0.f, 0.f, 0.f, 0.f};
        float c1[4] = {0.f, 0.f, 0.f, 0.f};

        const int arow = lane & 15;
        const int acolsel = (lane & 16) ? 16 : 0;
        const int brow = warp * 8 + (lane & 7);
        const int bcolsel = (lane & 8) ? 16 : 0;

        const int dr0 = t >> 3, ds = t & 7;
        const int dr1 = dr0 + 32;
        const int rr = t >> 3, rs = t & 7;

        auto load_stage = [&](int buf, int kb) {
            const size_t gk = (size_t)(kBase + kb);
            cpa16(smem_u32(&sD[buf][dr0][ds * 16]),
                  &g_dict_f8[(size_t)(atomBase + dr0) * DMODEL + gk + ds * 16]);
            cpa16(smem_u32(&sD[buf][dr1][ds * 16]),
                  &g_dict_f8[(size_t)(atomBase + dr1) * DMODEL + gk + ds * 16]);
            cpa16(smem_u32(&sR[buf][rr][rs * 16]),
                  &g_resid_f8[(size_t)rr * DMODEL + gk + rs * 16]);
            cpa_commit();
        };

        load_stage(0, 0);
        load_stage(1, KB);

        for (int s = 0; s < NSTEPS; s++) {
            if (s + NSTAGE - 1 < NSTEPS) load_stage((s + NSTAGE - 1) % NSTAGE, (s + NSTAGE - 1) * KB);
            else cpa_commit();
            cpa_wait2();
            __syncthreads();

            const int b = s % NSTAGE;
            #pragma unroll
            for (int ks = 0; ks < KB / 32; ks++) {
                uint32_t a0[4], a1[4], bb[2];
                const int col = ks * 32;
                ldsm_x4(a0, smem_u32(&sR[b][arow][col + acolsel]));
                ldsm_x4(a1, smem_u32(&sR[b][16 + arow][col + acolsel]));
                ldsm_x2(bb, smem_u32(&sD[b][brow][col + bcolsel]));
                mma16832(c0, a0, bb);
                mma16832(c1, a1, bb);
            }
            __syncthreads();
        }
        cpa_wait0();

        const int gr = lane >> 2;
        const int acol = atomBase + warp * 8 + (lane & 3) * 2;
        float* P = g_part + (size_t)(bx >> 6) * BATCH * ATOMS;
        P[(size_t)(gr + 0)  * ATOMS + acol]     = c0[0];
        P[(size_t)(gr + 0)  * ATOMS + acol + 1] = c0[1];
        P[(size_t)(gr + 8)  * ATOMS + acol]     = c0[2];
        P[(size_t)(gr + 8)  * ATOMS + acol + 1] = c0[3];
        P[(size_t)(gr + 16) * ATOMS + acol]     = c1[0];
        P[(size_t)(gr + 16) * ATOMS + acol + 1] = c1[1];
        P[(size_t)(gr + 24) * ATOMS + acol]     = c1[2];
        P[(size_t)(gr + 24) * ATOMS + acol + 1] = c1[3];
    }

    gbar(0);   // all partials final

    // ================= Phase B: reduce slice + row max + select ========
    const int r = bx & (BATCH - 1);
    const int slot = bx >> 5;              // 0..15
    const int myAtom = slot * 256 + t;

    float myScore;
    {
        float s = 0.f;
        #pragma unroll
        for (int c = 0; c < KCHUNKS; c++)
            s += g_part[((size_t)c * BATCH + r) * ATOMS + myAtom];
        myScore = s * INV_S;
    }
    {
        float lmax = myScore;
        #pragma unroll
        for (int o = 16; o > 0; o >>= 1) lmax = fmaxf(lmax, __shfl_xor_sync(0xffffffffu, lmax, o));
        if (lane == 0) sred[warp] = lmax;
        __syncthreads();
        if (t == 0) {
            float mm = sred[0];
            #pragma unroll
            for (int i = 1; i < 8; i++) mm = fmaxf(mm, sred[i]);
            atomicMax(&g_rowmax[r], fenc(mm));
        }
    }

    gbar(1);   // all row maxes final

    {
        const float thr = fdec(g_rowmax[r]) - WINDOW;
        if (myScore > thr) {
            int p = atomicAdd(&g_cnt[r], 1);
            if (p < MAXC) g_cand[r * MAXC + p] = myAtom;
        }
    }

    gbar(0);   // candidate lists complete

    // ================= Phase C: sort (identical) + exact rescore =======
    if (t == 0) {
        int n = min(g_cnt[r], MAXC);
        for (int i = 0; i < n; i++) s_idx[i] = g_cand[r * MAXC + i];
        for (int i = 1; i < n; i++) {
            int v = s_idx[i], j = i - 1;
            while (j >= 0 && s_idx[j] > v) { s_idx[j + 1] = s_idx[j]; j--; }
            s_idx[j + 1] = v;
        }
        s_n = n;
    }
    __syncthreads();
    const int n = s_n;

    {
        const float* R = g_resid + (size_t)r * DMODEL;
        for (int j = slot; j < n; j += SLOTS) {
            const float* D = dict + (size_t)s_idx[j] * DMODEL;
            float acc = 0.f;
            #pragma unroll 4
            for (int d = t * 4; d < DMODEL; d += 1024) {
                const float4 rv = *(const float4*)(R + d);
                const float4 dv = *(const float4*)(D + d);
                acc += rv.x * dv.x + rv.y * dv.y + rv.z * dv.z + rv.w * dv.w;
            }
            #pragma unroll
            for (int o = 16; o > 0; o >>= 1) acc += __shfl_xor_sync(0xffffffffu, acc, o);
            if (lane == 0) sred[warp] = acc;
            __syncthreads();
            if (t == 0) {
                float s = 0.f;
                #pragma unroll
                for (int i = 0; i < 8; i++) s += sred[i];
                g_ex[r * MAXC + j] = s;
            }
            __syncthreads();
        }
    }

    gbar(1);   // exact scores final

    // ================= Phase D: softmax + apply ========================
    if (t == 0) {
        float em = -1e30f;
        for (int j = 0; j < n; j++) em = fmaxf(em, g_ex[r * MAXC + j]);
        float den = 0.f;
        for (int j = 0; j < n; j++) {
            const float wv = expf((g_ex[r * MAXC + j] - em) / TEMP);
            s_w[j] = wv; den += wv;
        }
        const float inv = 1.f / den;
        for (int j = 0; j < n; j++) s_w[j] *= inv;
    }
    __syncthreads();

    {
        const int col = slot * 1024 + t * 4;
        const size_t base = (size_t)r * DMODEL + col;
        float4 v = *(const float4*)(g_resid + base);
        for (int j = 0; j < n; j++) {
            const float wj = s_w[j];
            const float4 dv = *(const float4*)(dict + (size_t)s_idx[j] * DMODEL + col);
            v.x -= wj * dv.x; v.y -= wj * dv.y; v.z -= wj * dv.z; v.w -= wj * dv.w;
        }
        *(float4*)(g_resid + base) = v;
        *(uint32_t*)(g_resid_f8 + base) =
            f8x4(v.x * RSCALE, v.y * RSCALE, v.z * RSCALE, v.w * RSCALE);
    }

    if (slot == 0 && t == 0) {
        g_cnt[r] = 0;
        g_rowmax[r] = 0u;
    }
}

// Fused epilogue: copy residual to out AND per-block square-sums.
__global__ void k_epilogue(float* out, int out_size) {
    __shared__ float s[256];
    const int b = blockIdx.x, t = threadIdx.x;
    const int off = (out_size > NRES) ? 1 : 0;
    const size_t base = (size_t)b * 1024;
    float acc = 0.f;
    #pragma unroll
    for (int i = 0; i < 4; i++) {
        const size_t idx = base + t + i * 256;
        const float v = g_resid[idx];
        out[off + idx] = v;
        acc += v * v;
    }
    s[t] = acc; __syncthreads();
    for (int o = 128; o > 0; o >>= 1) { if (t < o) s[t] += s[t + o]; __syncthreads(); }
    if (t == 0) g_lpart[b] = s[0];
}

__global__ void k_finalize(float* out, int out_size) {
    __shared__ float s[512];
    const int t = threadIdx.x;
    s[t] = g_lpart[t]; __syncthreads();
    for (int o = 256; o > 0; o >>= 1) { if (t < o) s[t] += s[t + o]; __syncthreads(); }
    if (t == 0 && out_size > NRES) out[0] = s[0] / (float)NRES;
}

// ---------------- launch ----------------------------------------------------
extern "C" void kernel_launch(void* const* d_in, const int* in_sizes, int n_in,
                              void* d_out, int out_size) {
    const float* x = nullptr;
    const float* dict = nullptr;
    for (int i = 0; i < n_in; i++) {
        if (in_sizes[i] == NRES) x = (const float*)d_in[i];
        else if (in_sizes[i] == ATOMS * DMODEL) dict = (const float*)d_in[i];
    }
    float* out = (float*)d_out;

    k_convert_dict<<<65536, 256>>>(dict);
    k_init<<<512, 256>>>(x);

    for (int it = 0; it < ITERS; it++)
        k_iter<<<GRID_I, 256>>>(dict);

    k_epilogue<<<512, 256>>>(out, out_size);
    k_finalize<<<1, 512>>>(out, out_size);
}

// round 11
// speedup vs baseline: 1.1918x; 1.0187x over previous
#include <cuda_runtime.h>
#include <cuda_bf16.h>
#include <cuda_fp8.h>
#include <stdint.h>

#define ATOMS   4096
#define DMODEL  16384
#define BATCH   32
#define ITERS   10
#define TEMP    0.001f

#define KCHUNKS 16
#define KCHUNK  (DMODEL / KCHUNKS)   // 1024
#define ATILE   128
#define NTILES  (ATOMS / ATILE)      // 32
#define KB      64                   // fp8 k elems per stage
#define NSTAGE  3
#define NSTEPS  (KCHUNK / KB)        // 16
#define MAXC    64
#define WINDOW  0.40f

#define DSCALE  8192.0f
#define RSCALE  32.0f
#define INV_S   (1.0f / (DSCALE * RSCALE))

#define SROW    (KB + 16)            // 80
#define NRES    (BATCH * DMODEL)     // 524288

#define GRID_I  512                  // = NTILES * KCHUNKS; all co-resident (4/SM)
#define SLOTS   16                   // update slots per row

// ---------------- persistent scratch --------------------------------------
__device__ uint8_t  g_dict_f8[(size_t)ATOMS * DMODEL];              // 64 MB
__device__ float    g_resid[(size_t)BATCH * DMODEL];                // 2 MB
__device__ uint8_t  g_resid_f8[(size_t)BATCH * DMODEL];             // 0.5 MB
__device__ float    g_part[(size_t)KCHUNKS * BATCH * ATOMS];        // 8 MB
__device__ unsigned g_rowmax[BATCH];
__device__ int      g_cnt[BATCH];
__device__ int      g_cand[BATCH * MAXC];
__device__ float    g_ex[BATCH * MAXC];
__device__ float    g_lpart[512];
__device__ unsigned g_bcnt[2];
__device__ unsigned g_bgen[2];

// ---------------- PTX helpers ----------------------------------------------
__device__ __forceinline__ uint32_t smem_u32(const void* p) {
    return (uint32_t)__cvta_generic_to_shared(p);
}
__device__ __forceinline__ void cpa16(uint32_t s, const void* g) {
    asm volatile("cp.async.cg.shared.global [%0], [%1], 16;\n" :: "r"(s), "l"(g));
}
__device__ __forceinline__ void cpa_commit() {
    asm volatile("cp.async.commit_group;\n");
}
__device__ __forceinline__ void cpa_wait2() {
    asm volatile("cp.async.wait_group 2;\n");
}
__device__ __forceinline__ void cpa_wait0() {
    asm volatile("cp.async.wait_group 0;\n");
}
__device__ __forceinline__ void ldsm_x4(uint32_t* r, uint32_t addr) {
    asm volatile("ldmatrix.sync.aligned.m8n8.x4.shared.b16 {%0,%1,%2,%3}, [%4];\n"
        : "=r"(r[0]), "=r"(r[1]), "=r"(r[2]), "=r"(r[3]) : "r"(addr));
}
__device__ __forceinline__ void ldsm_x2(uint32_t* r, uint32_t addr) {
    asm volatile("ldmatrix.sync.aligned.m8n8.x2.shared.b16 {%0,%1}, [%2];\n"
        : "=r"(r[0]), "=r"(r[1]) : "r"(addr));
}
__device__ __forceinline__ void mma16832(float* c, const uint32_t* a, const uint32_t* b) {
    asm volatile(
        "mma.sync.aligned.m16n8k32.row.col.f32.e4m3.e4m3.f32 "
        "{%0,%1,%2,%3}, {%4,%5,%6,%7}, {%8,%9}, {%0,%1,%2,%3};\n"
        : "+f"(c[0]), "+f"(c[1]), "+f"(c[2]), "+f"(c[3])
        : "r"(a[0]), "r"(a[1]), "r"(a[2]), "r"(a[3]), "r"(b[0]), "r"(b[1]));
}
__device__ __forceinline__ uint32_t f8x4(float x, float y, float z, float w) {
    __nv_fp8x4_e4m3 p(make_float4(x, y, z, w));
    return *(uint32_t*)&p;
}
__device__ __forceinline__ unsigned fenc(float v) {
    int b = __float_as_int(v);
    return (b >= 0) ? ((unsigned)b | 0x80000000u) : ~(unsigned)b;
}
__device__ __forceinline__ float fdec(unsigned k) {
    int b = (k & 0x80000000u) ? (int)(k & 0x7fffffffu) : ~(int)k;
    return __int_as_float(b);
}

// Generation-counter grid barrier (no reset needed across launches/replays).
__device__ __forceinline__ void gbar(int b) {
    __syncthreads();
    if (threadIdx.x == 0) {
        volatile unsigned* gen = &g_bgen[b];
        const unsigned g = *gen;
        __threadfence();
        const unsigned o = atomicAdd(&g_bcnt[b], 1u);
        if (o == GRID_I - 1) {
            g_bcnt[b] = 0;
            __threadfence();
            atomicAdd(&g_bgen[b], 1u);
        } else {
            while (*gen == g) __nanosleep(64);
        }
        __threadfence();
    }
    __syncthreads();
}

// ---------------- kernels ---------------------------------------------------

__global__ void k_convert_dict(const float* __restrict__ dict) {
    size_t i = ((size_t)blockIdx.x * blockDim.x + threadIdx.x) * 4;
    float4 v = *(const float4*)(dict + i);
    *(uint32_t*)(g_dict_f8 + i) =
        f8x4(v.x * DSCALE, v.y * DSCALE, v.z * DSCALE, v.w * DSCALE);
}

__global__ void k_init(const float* __restrict__ x) {
    size_t i = ((size_t)blockIdx.x * blockDim.x + threadIdx.x) * 4;
    float4 v = *(const float4*)(x + i);
    *(float4*)(g_resid + i) = v;
    *(uint32_t*)(g_resid_f8 + i) =
        f8x4(v.x * RSCALE, v.y * RSCALE, v.z * RSCALE, v.w * RSCALE);
    if (blockIdx.x == 0 && threadIdx.x < BATCH) {
        g_rowmax[threadIdx.x] = 0u;
        g_cnt[threadIdx.x] = 0;
    }
}

// One full MP iteration: scores -> reduce/select -> rescore -> apply.
// grid 512 x 256, all CTAs co-resident (launch_bounds forces 4/SM).
__global__ void __launch_bounds__(256, 4) k_iter(const float* __restrict__ dict) {
    __shared__ uint8_t sD[NSTAGE][ATILE][SROW];   // 3 x 128 x 80 = 30.0 KB
    __shared__ uint8_t sR[NSTAGE][BATCH][SROW];   // 3 x 32 x 80  =  7.5 KB
    __shared__ float   sred[8];
    __shared__ int     s_n;
    __shared__ int     s_idx[MAXC];
    __shared__ float   s_w[MAXC];

    const int t = threadIdx.x;
    const int lane = t & 31, warp = t >> 5;
    const int bx = blockIdx.x;

    // ================= Phase A: fp8 tensor-core scores =================
    // Tile: 128 atoms x 1024 k. 8 warps x 16 atoms each.
    {
        const int atomBase = (bx & (NTILES - 1)) * ATILE;
        const int kBase = (bx >> 5) * KCHUNK;

        float c0[2][4] = {{0.f,0.f,0.f,0.f},{0.f,0.f,0.f,0.f}};  // atoms +0..7  (rows 0-15, 16-31)
        float c1[2][4] = {{0.f,0.f,0.f,0.f},{0.f,0.f,0.f,0.f}};  // atoms +8..15

        const int arow = lane & 15;
        const int acolsel = (lane & 16) ? 16 : 0;
        const int brow0 = warp * 16 + (lane & 7);
        const int brow1 = brow0 + 8;
        const int bcolsel = (lane & 8) ? 16 : 0;

        // cp.async coords: dict 512 x 16B (2/thread), resid 128 x 16B (t<128)
        const int d0r = t >> 2,        d0s = t & 3;
        const int d1r = (t + 256) >> 2;               // seg same (t&3)
        const int rr = t >> 2,         rs = t & 3;

        auto load_stage = [&](int buf, int kb) {
            const size_t gk = (size_t)(kBase + kb);
            cpa16(smem_u32(&sD[buf][d0r][d0s * 16]),
                  &g_dict_f8[(size_t)(atomBase + d0r) * DMODEL + gk + d0s * 16]);
            cpa16(smem_u32(&sD[buf][d1r][d0s * 16]),
                  &g_dict_f8[(size_t)(atomBase + d1r) * DMODEL + gk + d0s * 16]);
            if (t < 128)
                cpa16(smem_u32(&sR[buf][rr][rs * 16]),
                      &g_resid_f8[(size_t)rr * DMODEL + gk + rs * 16]);
            cpa_commit();
        };

        load_stage(0, 0);
        load_stage(1, KB);

        for (int s = 0; s < NSTEPS; s++) {
            if (s + NSTAGE - 1 < NSTEPS) load_stage((s + NSTAGE - 1) % NSTAGE, (s + NSTAGE - 1) * KB);
            else cpa_commit();
            cpa_wait2();
            __syncthreads();

            const int b = s % NSTAGE;
            #pragma unroll
            for (int ks = 0; ks < KB / 32; ks++) {
                uint32_t a0[4], a1[4], b0[2], b1[2];
                const int col = ks * 32;
                ldsm_x4(a0, smem_u32(&sR[b][arow][col + acolsel]));
                ldsm_x4(a1, smem_u32(&sR[b][16 + arow][col + acolsel]));
                ldsm_x2(b0, smem_u32(&sD[b][brow0][col + bcolsel]));
                ldsm_x2(b1, smem_u32(&sD[b][brow1][col + bcolsel]));
                mma16832(c0[0], a0, b0);
                mma16832(c0[1], a1, b0);
                mma16832(c1[0], a0, b1);
                mma16832(c1[1], a1, b1);
            }
            __syncthreads();
        }
        cpa_wait0();

        const int gr = lane >> 2;
        float* P = g_part + (size_t)(bx >> 5) * BATCH * ATOMS;
        #pragma unroll
        for (int beta = 0; beta < 2; beta++) {
            const int ac = atomBase + warp * 16 + beta * 8 + (lane & 3) * 2;
            const float (*c)[4] = beta ? c1 : c0;
            #pragma unroll
            for (int h = 0; h < 2; h++) {
                P[(size_t)(gr + h * 16 + 0) * ATOMS + ac]     = c[h][0];
                P[(size_t)(gr + h * 16 + 0) * ATOMS + ac + 1] = c[h][1];
                P[(size_t)(gr + h * 16 + 8) * ATOMS + ac]     = c[h][2];
                P[(size_t)(gr + h * 16 + 8) * ATOMS + ac + 1] = c[h][3];
            }
        }
    }

    gbar(0);   // all partials final

    // ================= Phase B: reduce slice + row max + select ========
    const int r = bx & (BATCH - 1);
    const int slot = bx >> 5;              // 0..15
    const int myAtom = slot * 256 + t;

    float myScore;
    {
        float s = 0.f;
        #pragma unroll
        for (int c = 0; c < KCHUNKS; c++)
            s += g_part[((size_t)c * BATCH + r) * ATOMS + myAtom];
        myScore = s * INV_S;
    }
    {
        float lmax = myScore;
        #pragma unroll
        for (int o = 16; o > 0; o >>= 1) lmax = fmaxf(lmax, __shfl_xor_sync(0xffffffffu, lmax, o));
        if (lane == 0) sred[warp] = lmax;
        __syncthreads();
        if (t == 0) {
            float mm = sred[0];
            #pragma unroll
            for (int i = 1; i < 8; i++) mm = fmaxf(mm, sred[i]);
            atomicMax(&g_rowmax[r], fenc(mm));
        }
    }

    gbar(1);   // all row maxes final

    {
        const float thr = fdec(g_rowmax[r]) - WINDOW;
        if (myScore > thr) {
            int p = atomicAdd(&g_cnt[r], 1);
            if (p < MAXC) g_cand[r * MAXC + p] = myAtom;
        }
    }

    gbar(0);   // candidate lists complete

    // ================= Phase C: sort (identical) + exact rescore =======
    if (t == 0) {
        int n = min(g_cnt[r], MAXC);
        for (int i = 0; i < n; i++) s_idx[i] = g_cand[r * MAXC + i];
        for (int i = 1; i < n; i++) {
            int v = s_idx[i], j = i - 1;
            while (j >= 0 && s_idx[j] > v) { s_idx[j + 1] = s_idx[j]; j--; }
            s_idx[j + 1] = v;
        }
        s_n = n;
    }
    __syncthreads();
    const int n = s_n;

    {
        const float* R = g_resid + (size_t)r * DMODEL;
        for (int j = slot; j < n; j += SLOTS) {
            const float* D = dict + (size_t)s_idx[j] * DMODEL;
            float acc = 0.f;
            #pragma unroll 4
            for (int d = t * 4; d < DMODEL; d += 1024) {
                const float4 rv = *(const float4*)(R + d);
                const float4 dv = *(const float4*)(D + d);
                acc += rv.x * dv.x + rv.y * dv.y + rv.z * dv.z + rv.w * dv.w;
            }
            #pragma unroll
            for (int o = 16; o > 0; o >>= 1) acc += __shfl_xor_sync(0xffffffffu, acc, o);
            if (lane == 0) sred[warp] = acc;
            __syncthreads();
            if (t == 0) {
                float s = 0.f;
                #pragma unroll
                for (int i = 0; i < 8; i++) s += sred[i];
                g_ex[r * MAXC + j] = s;
            }
            __syncthreads();
        }
    }

    gbar(1);   // exact scores final

    // ================= Phase D: softmax + apply ========================
    if (t == 0) {
        float em = -1e30f;
        for (int j = 0; j < n; j++) em = fmaxf(em, g_ex[r * MAXC + j]);
        float den = 0.f;
        for (int j = 0; j < n; j++) {
            const float wv = expf((g_ex[r * MAXC + j] - em) / TEMP);
            s_w[j] = wv; den += wv;
        }
        const float inv = 1.f / den;
        for (int j = 0; j < n; j++) s_w[j] *= inv;
    }
    __syncthreads();

    {
        const int col = slot * 1024 + t * 4;
        const size_t base = (size_t)r * DMODEL + col;
        float4 v = *(const float4*)(g_resid + base);
        for (int j = 0; j < n; j++) {
            const float wj = s_w[j];
            const float4 dv = *(const float4*)(dict + (size_t)s_idx[j] * DMODEL + col);
            v.x -= wj * dv.x; v.y -= wj * dv.y; v.z -= wj * dv.z; v.w -= wj * dv.w;
        }
        *(float4*)(g_resid + base) = v;
        *(uint32_t*)(g_resid_f8 + base) =
            f8x4(v.x * RSCALE, v.y * RSCALE, v.z * RSCALE, v.w * RSCALE);
    }

    if (slot == 0 && t == 0) {
        g_cnt[r] = 0;
        g_rowmax[r] = 0u;
    }
}

// Fused epilogue: copy residual to out AND per-block square-sums.
__global__ void k_epilogue(float* out, int out_size) {
    __shared__ float s[256];
    const int b = blockIdx.x, t = threadIdx.x;
    const int off = (out_size > NRES) ? 1 : 0;
    const size_t base = (size_t)b * 1024;
    float acc = 0.f;
    #pragma unroll
    for (int i = 0; i < 4; i++) {
        const size_t idx = base + t + i * 256;
        const float v = g_resid[idx];
        out[off + idx] = v;
        acc += v * v;
    }
    s[t] = acc; __syncthreads();
    for (int o = 128; o > 0; o >>= 1) { if (t < o) s[t] += s[t + o]; __syncthreads(); }
    if (t == 0) g_lpart[b] = s[0];
}

__global__ void k_finalize(float* out, int out_size) {
    __shared__ float s[512];
    const int t = threadIdx.x;
    s[t] = g_lpart[t]; __syncthreads();
    for (int o = 256; o > 0; o >>= 1) { if (t < o) s[t] += s[t + o]; __syncthreads(); }
    if (t == 0 && out_size > NRES) out[0] = s[0] / (float)NRES;
}

// ---------------- launch ----------------------------------------------------
extern "C" void kernel_launch(void* const* d_in, const int* in_sizes, int n_in,
                              void* d_out, int out_size) {
    const float* x = nullptr;
    const float* dict = nullptr;
    for (int i = 0; i < n_in; i++) {
        if (in_sizes[i] == NRES) x = (const float*)d_in[i];
        else if (in_sizes[i] == ATOMS * DMODEL) dict = (const float*)d_in[i];
    }
    float* out = (float*)d_out;

    k_convert_dict<<<65536, 256>>>(dict);
    k_init<<<512, 256>>>(x);

    for (int it = 0; it < ITERS; it++)
        k_iter<<<GRID_I, 256>>>(dict);

    k_epilogue<<<512, 256>>>(out, out_size);
    k_finalize<<<1, 512>>>(out, out_size);
}